// round 4
// baseline (speedup 1.0000x reference)
#include <cuda_runtime.h>

#define A_ANG 192
#define DDET  576
#define W_IMG 384
#define PADW  1152
#define POFF  256

// Scratch (__device__ globals: allocation-free). g_pad is zero-initialized at
// module load; padding columns are never written, so they stay zero across
// all graph replays (out-of-range detector taps contribute exactly 0).
__device__ float2 g_pad[A_ANG * PADW];     // (sino, sino_pred) packed, padded
__device__ float  g_img[W_IMG * W_IMG];    // backprojection of raw sino

// ---------------------------------------------------------------------------
// Kernel 1: composite conv (sino -> sino_pred) + packed padded sinogram write.
// Each block builds the composite tables in smem (cheap, removes a launch):
//   G[d][e] = sum_c w2[c,d]*w1[c,e],  B[d] = sum_c w2[c,d]*b1[c]
//   W9[a][b] = sum_{d+e=(a,b)} G[d][e],  bias = b2 + sum_d B[d]
// Interior pixels: 9x9 kernel (81 FMA). Border pixels: exact per-d formula.
// ---------------------------------------------------------------------------
#define CTX 32
#define CTY 8
__global__ void __launch_bounds__(CTX * CTY) conv12_kernel(
    const float* __restrict__ sino,
    const float* __restrict__ w1, const float* __restrict__ b1,
    const float* __restrict__ w2, const float* __restrict__ b2,
    float* __restrict__ sino_pred)
{
    __shared__ float t[CTY + 8][CTX + 8];   // 16 x 40, halo 4, zero-padded
    __shared__ float sG[625];
    __shared__ float sW[81];
    __shared__ float sB[25];
    __shared__ float sbias;

    const int tid = threadIdx.y * CTX + threadIdx.x;

    // tables
    for (int i = tid; i < 625; i += CTX * CTY) {
        int d = i / 25, e = i % 25;
        float g = 0.0f;
        #pragma unroll
        for (int c = 0; c < 16; c++) g = fmaf(w2[c * 25 + d], w1[c * 25 + e], g);
        sG[i] = g;
    }
    if (tid < 25) {
        float s = 0.0f;
        #pragma unroll
        for (int c = 0; c < 16; c++) s = fmaf(w2[c * 25 + tid], b1[c], s);
        sB[tid] = s;
    }
    // input tile
    const int bx0 = blockIdx.x * CTX, by0 = blockIdx.y * CTY;
    for (int i = tid; i < (CTY + 8) * (CTX + 8); i += CTX * CTY) {
        int ly = i / (CTX + 8), lx = i % (CTX + 8);
        int gy = by0 - 4 + ly, gx = bx0 - 4 + lx;
        float v = 0.0f;
        if ((unsigned)gy < A_ANG && (unsigned)gx < DDET) v = sino[gy * DDET + gx];
        t[ly][lx] = v;
    }
    __syncthreads();

    if (tid < 81) {
        int tty = tid / 9, ttx = tid % 9;
        float w = 0.0f;
        for (int dy = 0; dy < 5; dy++) {
            int ey = tty - dy; if (ey < 0 || ey > 4) continue;
            for (int dx = 0; dx < 5; dx++) {
                int ex = ttx - dx; if (ex < 0 || ex > 4) continue;
                w += sG[(dy * 5 + dx) * 25 + ey * 5 + ex];
            }
        }
        sW[tid] = w;
    }
    if (tid == 255) {
        float bias = b2[0];
        #pragma unroll
        for (int d = 0; d < 25; d++) bias += sB[d];
        sbias = bias;
    }
    __syncthreads();

    const int tx = threadIdx.x, ty = threadIdx.y;
    const int gx = bx0 + tx, gy = by0 + ty;
    float acc;
    const bool interior = (gy >= 2) && (gy <= A_ANG - 3) && (gx >= 2) && (gx <= DDET - 3);
    if (interior) {
        acc = sbias;
        #pragma unroll
        for (int a = 0; a < 9; a++)
            #pragma unroll
            for (int b = 0; b < 9; b++)
                acc = fmaf(t[ty + a][tx + b], sW[a * 9 + b], acc);
    } else {
        acc = b2[0];
        for (int dy = 0; dy < 5; dy++) {
            int hy = gy + dy - 2; if ((unsigned)hy >= A_ANG) continue;
            for (int dx = 0; dx < 5; dx++) {
                int hx = gx + dx - 2; if ((unsigned)hx >= DDET) continue;
                float a2 = sB[dy * 5 + dx];
                #pragma unroll
                for (int ey = 0; ey < 5; ey++)
                    #pragma unroll
                    for (int ex = 0; ex < 5; ex++)
                        a2 = fmaf(t[ty + dy + ey][tx + dx + ex],
                                  sG[(dy * 5 + dx) * 25 + ey * 5 + ex], a2);
                acc += a2;
            }
        }
    }
    const int idx = gy * DDET + gx;
    sino_pred[idx] = acc;
    g_pad[gy * PADW + POFF + gx] = make_float2(t[ty + 4][tx + 4], acc);
}

// ---------------------------------------------------------------------------
// Kernel 2: dual fan-beam backprojection, 4 pixels/thread (same row),
// incremental geometry, 8 independent LDG.64 chains per angle iteration.
// ---------------------------------------------------------------------------
__global__ void __launch_bounds__(256) backproj_kernel(
    const float* __restrict__ angles,
    float* __restrict__ img_sino)
{
    __shared__ float s_cb[A_ANG], s_sb[A_ANG];
    const int tid = threadIdx.x;
    if (tid < A_ANG) {
        float sv, cv;
        sincosf(angles[tid], &sv, &cv);
        s_cb[tid] = cv; s_sb[tid] = sv;
    }
    __syncthreads();

    const int p = (blockIdx.x * 256 + tid) * 4;       // 4 consecutive px, same row
    const int x = p % W_IMG, y = p / W_IMG;
    const float X0 = (float)x - 191.5f;
    const float Y  = (float)y - 191.5f;

    float accA[4] = {0.f, 0.f, 0.f, 0.f};   // raw sino
    float accB[4] = {0.f, 0.f, 0.f, 0.f};   // sino_pred
    #pragma unroll 2
    for (int a = 0; a < A_ANG; a++) {
        const float cb = s_cb[a], sb = s_sb[a];
        const float px0 = fmaf(cb, X0, sb * Y);
        const float py0 = fmaf(-sb, X0, cb * Y);
        const float2* __restrict__ row = &g_pad[a * PADW + POFF];

        float2 v0[4], v1[4];
        float fr[4];
        #pragma unroll
        for (int k = 0; k < 4; k++) {
            const float px = px0 + (float)k * cb;
            const float py = py0 - (float)k * sb;
            const float f  = __fdividef(576.0f, 576.0f + py);
            const float s  = fmaf(px, f, 287.5f);
            const int i0   = __float2int_rd(s);
            fr[k] = s - (float)i0;
            v0[k] = row[i0];
            v1[k] = row[i0 + 1];
        }
        #pragma unroll
        for (int k = 0; k < 4; k++) {
            const float w0 = 1.0f - fr[k];
            accA[k] = fmaf(v0[k].x, w0, accA[k]);
            accA[k] = fmaf(v1[k].x, fr[k], accA[k]);
            accB[k] = fmaf(v0[k].y, w0, accB[k]);
            accB[k] = fmaf(v1[k].y, fr[k], accB[k]);
        }
    }
    #pragma unroll
    for (int k = 0; k < 4; k++) {
        g_img[p + k]    = accA[k];
        img_sino[p + k] = accB[k];
    }
}

// ---------------------------------------------------------------------------
// Kernel 3: conv3 (2->1, 3x3, pad1), smem-tiled (2 global loads per thread).
// ---------------------------------------------------------------------------
#define DTX 32
#define DTY 8
__global__ void __launch_bounds__(DTX * DTY) conv3_kernel(
    const float* __restrict__ w3, const float* __restrict__ b3,
    const float* __restrict__ img_sino,
    float* __restrict__ img_pred)
{
    __shared__ float sI[DTY + 2][DTX + 2];
    __shared__ float sS[DTY + 2][DTX + 2];
    __shared__ float s_w[18];
    __shared__ float s_b;

    const int tid = threadIdx.y * DTX + threadIdx.x;
    if (tid < 18) s_w[tid] = w3[tid];
    if (tid == 18) s_b = b3[0];

    const int bx0 = blockIdx.x * DTX, by0 = blockIdx.y * DTY;
    for (int i = tid; i < (DTY + 2) * (DTX + 2); i += DTX * DTY) {
        int ly = i / (DTX + 2), lx = i % (DTX + 2);
        int gy = by0 - 1 + ly, gx = bx0 - 1 + lx;
        float vi = 0.0f, vs = 0.0f;
        if ((unsigned)gy < W_IMG && (unsigned)gx < W_IMG) {
            int q = gy * W_IMG + gx;
            vi = g_img[q];
            vs = __ldg(&img_sino[q]);
        }
        sI[ly][lx] = vi;
        sS[ly][lx] = vs;
    }
    __syncthreads();

    const int tx = threadIdx.x, ty = threadIdx.y;
    float acc = s_b;
    #pragma unroll
    for (int ky = 0; ky < 3; ky++)
        #pragma unroll
        for (int kx = 0; kx < 3; kx++) {
            acc = fmaf(sI[ty + ky][tx + kx], s_w[ky * 3 + kx],     acc);
            acc = fmaf(sS[ty + ky][tx + kx], s_w[9 + ky * 3 + kx], acc);
        }
    img_pred[(by0 + ty) * W_IMG + bx0 + tx] = acc;
}

// ---------------------------------------------------------------------------
extern "C" void kernel_launch(void* const* d_in, const int* in_sizes, int n_in,
                              void* d_out, int out_size)
{
    const float* sino   = (const float*)d_in[0];
    const float* angles = (const float*)d_in[1];
    const float* w1     = (const float*)d_in[2];
    const float* b1     = (const float*)d_in[3];
    const float* w2     = (const float*)d_in[4];
    const float* b2     = (const float*)d_in[5];
    const float* w3     = (const float*)d_in[6];
    const float* b3     = (const float*)d_in[7];

    float* out       = (float*)d_out;
    float* sino_pred = out;                               // 192*576 = 110592
    float* img_sino  = out + A_ANG * DDET;                // 384*384 = 147456
    float* img_pred  = out + A_ANG * DDET + W_IMG * W_IMG;

    dim3 grid1(DDET / CTX, A_ANG / CTY);
    dim3 block1(CTX, CTY);
    conv12_kernel<<<grid1, block1>>>(sino, w1, b1, w2, b2, sino_pred);

    backproj_kernel<<<(W_IMG * W_IMG) / 1024, 256>>>(angles, img_sino);

    dim3 grid3(W_IMG / DTX, W_IMG / DTY);
    dim3 block3(DTX, DTY);
    conv3_kernel<<<grid3, block3>>>(w3, b3, img_sino, img_pred);
}

// round 5
// speedup vs baseline: 1.2503x; 1.2503x over previous
#include <cuda_runtime.h>

#define A_ANG 192
#define DDET  576
#define W_IMG 384
#define PADW  1152
#define POFF  256

// Scratch (__device__ globals: allocation-free). g_pad is zero-initialized at
// module load; padding columns are never written, so they stay zero across
// all graph replays (out-of-range detector taps contribute exactly 0).
__device__ float2 g_pad[A_ANG * PADW];     // (sino, sino_pred) packed, padded
__device__ float  g_img[W_IMG * W_IMG];    // backprojection of raw sino
__device__ float  g_G[625];                // G[d][e] = sum_c w2[c,d]*w1[c,e]
__device__ float  g_B[25];                 // B[d]    = sum_c w2[c,d]*b1[c]
__device__ float  g_W[81];                 // interior 9x9 composite kernel
__device__ float  g_bias[1];               // b2 + sum_d B[d]

// ---------------------------------------------------------------------------
// Kernel 0: build composite-conv tables (1 block, trivial cost)
// ---------------------------------------------------------------------------
__global__ void __launch_bounds__(640) precompute_kernel(
    const float* __restrict__ w1, const float* __restrict__ b1,
    const float* __restrict__ w2, const float* __restrict__ b2)
{
    __shared__ float sG[625];
    const int tid = threadIdx.x;
    if (tid < 625) {
        int d = tid / 25, e = tid % 25;
        float g = 0.0f;
        #pragma unroll
        for (int c = 0; c < 16; c++) g = fmaf(w2[c * 25 + d], w1[c * 25 + e], g);
        sG[tid] = g;
        g_G[tid] = g;
    }
    if (tid < 25) {
        float s = 0.0f;
        #pragma unroll
        for (int c = 0; c < 16; c++) s = fmaf(w2[c * 25 + tid], b1[c], s);
        g_B[tid] = s;
    }
    __syncthreads();
    if (tid < 81) {
        int tty = tid / 9, ttx = tid % 9;
        float w = 0.0f;
        for (int dy = 0; dy < 5; dy++) {
            int ey = tty - dy; if (ey < 0 || ey > 4) continue;
            for (int dx = 0; dx < 5; dx++) {
                int ex = ttx - dx; if (ex < 0 || ex > 4) continue;
                w += sG[(dy * 5 + dx) * 25 + ey * 5 + ex];
            }
        }
        g_W[tid] = w;
    }
    if (tid == 0) {
        float bias = b2[0];
        #pragma unroll
        for (int c = 0; c < 16; c++) {
            float s2 = 0.0f;
            #pragma unroll
            for (int d = 0; d < 25; d++) s2 += w2[c * 25 + d];
            bias = fmaf(s2, b1[c], bias);
        }
        g_bias[0] = bias;
    }
}

// ---------------------------------------------------------------------------
// Kernel 1: composite conv (sino -> sino_pred), writes packed padded sinogram.
// Interior pixels: 9x9 kernel W (81 FMA). Border pixels: exact per-d formula.
// ---------------------------------------------------------------------------
#define CTX 32
#define CTY 8
__global__ void __launch_bounds__(CTX * CTY) conv12_kernel(
    const float* __restrict__ sino,
    const float* __restrict__ b2,
    float* __restrict__ sino_pred)
{
    __shared__ float t[CTY + 8][CTX + 8];   // 16 x 40, halo 4, zero-padded
    __shared__ float sW[81];
    __shared__ float sG[625];
    __shared__ float sB[25];
    __shared__ float sbias;

    const int tid = threadIdx.y * CTX + threadIdx.x;
    if (tid < 81) sW[tid] = g_W[tid];
    for (int i = tid; i < 625; i += CTX * CTY) sG[i] = g_G[i];
    if (tid < 25) sB[tid] = g_B[tid];
    if (tid == 255) sbias = g_bias[0];

    const int bx0 = blockIdx.x * CTX, by0 = blockIdx.y * CTY;
    for (int i = tid; i < (CTY + 8) * (CTX + 8); i += CTX * CTY) {
        int ly = i / (CTX + 8), lx = i % (CTX + 8);
        int gy = by0 - 4 + ly, gx = bx0 - 4 + lx;
        float v = 0.0f;
        if ((unsigned)gy < A_ANG && (unsigned)gx < DDET) v = sino[gy * DDET + gx];
        t[ly][lx] = v;
    }
    __syncthreads();

    const int tx = threadIdx.x, ty = threadIdx.y;
    const int gx = bx0 + tx, gy = by0 + ty;
    float acc;
    const bool interior = (gy >= 2) && (gy <= A_ANG - 3) && (gx >= 2) && (gx <= DDET - 3);
    if (interior) {
        acc = sbias;
        #pragma unroll
        for (int a = 0; a < 9; a++)
            #pragma unroll
            for (int b = 0; b < 9; b++)
                acc = fmaf(t[ty + a][tx + b], sW[a * 9 + b], acc);
    } else {
        acc = b2[0];
        for (int dy = 0; dy < 5; dy++) {
            int hy = gy + dy - 2; if ((unsigned)hy >= A_ANG) continue;
            for (int dx = 0; dx < 5; dx++) {
                int hx = gx + dx - 2; if ((unsigned)hx >= DDET) continue;
                float a2 = sB[dy * 5 + dx];
                #pragma unroll
                for (int ey = 0; ey < 5; ey++)
                    #pragma unroll
                    for (int ex = 0; ex < 5; ex++)
                        a2 = fmaf(t[ty + dy + ey][tx + dx + ex],
                                  sG[(dy * 5 + dx) * 25 + ey * 5 + ex], a2);
                acc += a2;
            }
        }
    }
    const int idx = gy * DDET + gx;
    sino_pred[idx] = acc;
    g_pad[gy * PADW + POFF + gx] = make_float2(t[ty + 4][tx + 4], acc);
}

// ---------------------------------------------------------------------------
// Kernel 2: dual fan-beam backprojection.
// 2 pixels/thread (288 blocks -> ~16 warps/SM) x angle-pair unroll
// = 4 independent geometry chains / 8 outstanding LDG.64 per iteration.
// ---------------------------------------------------------------------------
__global__ void __launch_bounds__(256) backproj_kernel(
    const float* __restrict__ angles,
    float* __restrict__ img_sino)
{
    __shared__ float s_cb[A_ANG], s_sb[A_ANG];
    const int tid = threadIdx.x;
    if (tid < A_ANG) {
        float sv, cv;
        sincosf(angles[tid], &sv, &cv);
        s_cb[tid] = cv; s_sb[tid] = sv;
    }
    __syncthreads();

    const int p = (blockIdx.x * 256 + tid) * 2;     // 2 consecutive px, same row
    const int x = p % W_IMG, y = p / W_IMG;
    const float X0 = (float)x - 191.5f;
    const float Y  = (float)y - 191.5f;

    float a00 = 0.f, a01 = 0.f;     // pixel0: (sino, sino_pred)
    float a10 = 0.f, a11 = 0.f;     // pixel1
    for (int a = 0; a < A_ANG; a += 2) {
        float2 v0[4], v1[4];
        float fr[4];
        #pragma unroll
        for (int j = 0; j < 2; j++) {               // angle pair
            const float cb = s_cb[a + j], sb = s_sb[a + j];
            const float px0 = fmaf(cb, X0, sb * Y);
            const float py0 = fmaf(-sb, X0, cb * Y);
            const float2* __restrict__ row = &g_pad[(a + j) * PADW + POFF];
            #pragma unroll
            for (int k = 0; k < 2; k++) {           // pixel pair
                const int c = j * 2 + k;
                const float px = px0 + (float)k * cb;
                const float py = py0 - (float)k * sb;
                const float f  = __fdividef(576.0f, 576.0f + py);
                const float s  = fmaf(px, f, 287.5f);
                const int i0   = __float2int_rd(s);
                fr[c] = s - (float)i0;
                v0[c] = row[i0];
                v1[c] = row[i0 + 1];
            }
        }
        #pragma unroll
        for (int j = 0; j < 2; j++) {
            const float w0a = 1.0f - fr[j * 2 + 0];
            const float w0b = 1.0f - fr[j * 2 + 1];
            a00 = fmaf(v0[j * 2 + 0].x, w0a,         a00);
            a00 = fmaf(v1[j * 2 + 0].x, fr[j * 2 + 0], a00);
            a01 = fmaf(v0[j * 2 + 0].y, w0a,         a01);
            a01 = fmaf(v1[j * 2 + 0].y, fr[j * 2 + 0], a01);
            a10 = fmaf(v0[j * 2 + 1].x, w0b,         a10);
            a10 = fmaf(v1[j * 2 + 1].x, fr[j * 2 + 1], a10);
            a11 = fmaf(v0[j * 2 + 1].y, w0b,         a11);
            a11 = fmaf(v1[j * 2 + 1].y, fr[j * 2 + 1], a11);
        }
    }
    g_img[p]     = a00;  g_img[p + 1]    = a10;
    img_sino[p]  = a01;  img_sino[p + 1] = a11;
}

// ---------------------------------------------------------------------------
// Kernel 3: conv3 (2->1, 3x3, pad1), smem-tiled (2 global loads per thread).
// ---------------------------------------------------------------------------
#define DTX 32
#define DTY 8
__global__ void __launch_bounds__(DTX * DTY) conv3_kernel(
    const float* __restrict__ w3, const float* __restrict__ b3,
    const float* __restrict__ img_sino,
    float* __restrict__ img_pred)
{
    __shared__ float sI[DTY + 2][DTX + 2];
    __shared__ float sS[DTY + 2][DTX + 2];
    __shared__ float s_w[18];
    __shared__ float s_b;

    const int tid = threadIdx.y * DTX + threadIdx.x;
    if (tid < 18) s_w[tid] = w3[tid];
    if (tid == 18) s_b = b3[0];

    const int bx0 = blockIdx.x * DTX, by0 = blockIdx.y * DTY;
    for (int i = tid; i < (DTY + 2) * (DTX + 2); i += DTX * DTY) {
        int ly = i / (DTX + 2), lx = i % (DTX + 2);
        int gy = by0 - 1 + ly, gx = bx0 - 1 + lx;
        float vi = 0.0f, vs = 0.0f;
        if ((unsigned)gy < W_IMG && (unsigned)gx < W_IMG) {
            int q = gy * W_IMG + gx;
            vi = g_img[q];
            vs = __ldg(&img_sino[q]);
        }
        sI[ly][lx] = vi;
        sS[ly][lx] = vs;
    }
    __syncthreads();

    const int tx = threadIdx.x, ty = threadIdx.y;
    float acc = s_b;
    #pragma unroll
    for (int ky = 0; ky < 3; ky++)
        #pragma unroll
        for (int kx = 0; kx < 3; kx++) {
            acc = fmaf(sI[ty + ky][tx + kx], s_w[ky * 3 + kx],     acc);
            acc = fmaf(sS[ty + ky][tx + kx], s_w[9 + ky * 3 + kx], acc);
        }
    img_pred[(by0 + ty) * W_IMG + bx0 + tx] = acc;
}

// ---------------------------------------------------------------------------
extern "C" void kernel_launch(void* const* d_in, const int* in_sizes, int n_in,
                              void* d_out, int out_size)
{
    const float* sino   = (const float*)d_in[0];
    const float* angles = (const float*)d_in[1];
    const float* w1     = (const float*)d_in[2];
    const float* b1     = (const float*)d_in[3];
    const float* w2     = (const float*)d_in[4];
    const float* b2     = (const float*)d_in[5];
    const float* w3     = (const float*)d_in[6];
    const float* b3     = (const float*)d_in[7];

    float* out       = (float*)d_out;
    float* sino_pred = out;                               // 192*576 = 110592
    float* img_sino  = out + A_ANG * DDET;                // 384*384 = 147456
    float* img_pred  = out + A_ANG * DDET + W_IMG * W_IMG;

    precompute_kernel<<<1, 640>>>(w1, b1, w2, b2);

    dim3 grid1(DDET / CTX, A_ANG / CTY);
    dim3 block1(CTX, CTY);
    conv12_kernel<<<grid1, block1>>>(sino, b2, sino_pred);

    backproj_kernel<<<(W_IMG * W_IMG) / 512, 256>>>(angles, img_sino);

    dim3 grid3(W_IMG / DTX, W_IMG / DTY);
    dim3 block3(DTX, DTY);
    conv3_kernel<<<grid3, block3>>>(w3, b3, img_sino, img_pred);
}

// round 6
// speedup vs baseline: 1.5660x; 1.2525x over previous
#include <cuda_runtime.h>

#define A_ANG 192
#define DDET  576
#define W_IMG 384
#define PADW  1152
#define POFF  256

// Scratch (__device__ globals: allocation-free). g_pad is zero-initialized at
// module load; padding columns are never written, so they stay zero across
// all graph replays (out-of-range detector taps contribute exactly 0).
__device__ float2 g_pad[A_ANG * PADW];     // (sino, sino_pred) packed, padded
__device__ float  g_img[W_IMG * W_IMG];    // backprojection of raw sino
__device__ float  g_G[625];                // G[d][e] = sum_c w2[c,d]*w1[c,e]
__device__ float  g_B[25];                 // B[d]    = sum_c w2[c,d]*b1[c]
__device__ float  g_W[81];                 // interior 9x9 composite kernel
__device__ float  g_bias[1];               // b2 + sum_d B[d]

// ---------------------------------------------------------------------------
// Kernel 0: build composite-conv tables (1 block, trivial cost)
// ---------------------------------------------------------------------------
__global__ void __launch_bounds__(640) precompute_kernel(
    const float* __restrict__ w1, const float* __restrict__ b1,
    const float* __restrict__ w2, const float* __restrict__ b2)
{
    __shared__ float sG[625];
    const int tid = threadIdx.x;
    if (tid < 625) {
        int d = tid / 25, e = tid % 25;
        float g = 0.0f;
        #pragma unroll
        for (int c = 0; c < 16; c++) g = fmaf(w2[c * 25 + d], w1[c * 25 + e], g);
        sG[tid] = g;
        g_G[tid] = g;
    }
    if (tid < 25) {
        float s = 0.0f;
        #pragma unroll
        for (int c = 0; c < 16; c++) s = fmaf(w2[c * 25 + tid], b1[c], s);
        g_B[tid] = s;
    }
    __syncthreads();
    if (tid < 81) {
        int tty = tid / 9, ttx = tid % 9;
        float w = 0.0f;
        for (int dy = 0; dy < 5; dy++) {
            int ey = tty - dy; if (ey < 0 || ey > 4) continue;
            for (int dx = 0; dx < 5; dx++) {
                int ex = ttx - dx; if (ex < 0 || ex > 4) continue;
                w += sG[(dy * 5 + dx) * 25 + ey * 5 + ex];
            }
        }
        g_W[tid] = w;
    }
    if (tid == 0) {
        float bias = b2[0];
        #pragma unroll
        for (int c = 0; c < 16; c++) {
            float s2 = 0.0f;
            #pragma unroll
            for (int d = 0; d < 25; d++) s2 += w2[c * 25 + d];
            bias = fmaf(s2, b1[c], bias);
        }
        g_bias[0] = bias;
    }
}

// ---------------------------------------------------------------------------
// Kernel 1: composite conv (sino -> sino_pred), writes packed padded sinogram.
// Interior pixels: 9x9 kernel W (81 FMA). Border pixels: exact per-d formula.
// ---------------------------------------------------------------------------
#define CTX 32
#define CTY 8
__global__ void __launch_bounds__(CTX * CTY) conv12_kernel(
    const float* __restrict__ sino,
    const float* __restrict__ b2,
    float* __restrict__ sino_pred)
{
    __shared__ float t[CTY + 8][CTX + 8];   // 16 x 40, halo 4, zero-padded
    __shared__ float sW[81];
    __shared__ float sG[625];
    __shared__ float sB[25];
    __shared__ float sbias;

    const int tid = threadIdx.y * CTX + threadIdx.x;
    if (tid < 81) sW[tid] = g_W[tid];
    for (int i = tid; i < 625; i += CTX * CTY) sG[i] = g_G[i];
    if (tid < 25) sB[tid] = g_B[tid];
    if (tid == 255) sbias = g_bias[0];

    const int bx0 = blockIdx.x * CTX, by0 = blockIdx.y * CTY;
    for (int i = tid; i < (CTY + 8) * (CTX + 8); i += CTX * CTY) {
        int ly = i / (CTX + 8), lx = i % (CTX + 8);
        int gy = by0 - 4 + ly, gx = bx0 - 4 + lx;
        float v = 0.0f;
        if ((unsigned)gy < A_ANG && (unsigned)gx < DDET) v = sino[gy * DDET + gx];
        t[ly][lx] = v;
    }
    __syncthreads();

    const int tx = threadIdx.x, ty = threadIdx.y;
    const int gx = bx0 + tx, gy = by0 + ty;
    float acc;
    const bool interior = (gy >= 2) && (gy <= A_ANG - 3) && (gx >= 2) && (gx <= DDET - 3);
    if (interior) {
        acc = sbias;
        #pragma unroll
        for (int a = 0; a < 9; a++)
            #pragma unroll
            for (int b = 0; b < 9; b++)
                acc = fmaf(t[ty + a][tx + b], sW[a * 9 + b], acc);
    } else {
        acc = b2[0];
        for (int dy = 0; dy < 5; dy++) {
            int hy = gy + dy - 2; if ((unsigned)hy >= A_ANG) continue;
            for (int dx = 0; dx < 5; dx++) {
                int hx = gx + dx - 2; if ((unsigned)hx >= DDET) continue;
                float a2 = sB[dy * 5 + dx];
                #pragma unroll
                for (int ey = 0; ey < 5; ey++)
                    #pragma unroll
                    for (int ex = 0; ex < 5; ex++)
                        a2 = fmaf(t[ty + dy + ey][tx + dx + ex],
                                  sG[(dy * 5 + dx) * 25 + ey * 5 + ex], a2);
                acc += a2;
            }
        }
    }
    const int idx = gy * DDET + gx;
    sino_pred[idx] = acc;
    g_pad[gy * PADW + POFF + gx] = make_float2(t[ty + 4][tx + 4], acc);
}

// ---------------------------------------------------------------------------
// Kernel 2: dual fan-beam backprojection, 16x16 pixel tiles (L1 locality).
// Per-block detector working set ~69KB across all angles -> L1-resident.
// 1 px/thread, 2-angle unroll = 2 independent gather chains.
// ---------------------------------------------------------------------------
__global__ void __launch_bounds__(256) backproj_kernel(
    const float* __restrict__ angles,
    float* __restrict__ img_sino)
{
    __shared__ float s_cb[A_ANG], s_sb[A_ANG];
    const int tid = threadIdx.x;
    if (tid < A_ANG) {
        float sv, cv;
        sincosf(angles[tid], &sv, &cv);
        s_cb[tid] = cv; s_sb[tid] = sv;
    }
    __syncthreads();

    const int tx = tid & 15, ty = tid >> 4;
    const int x = blockIdx.x * 16 + tx;
    const int y = blockIdx.y * 16 + ty;
    const float X = (float)x - 191.5f;
    const float Y = (float)y - 191.5f;

    float accA = 0.f, accB = 0.f;
    for (int a = 0; a < A_ANG; a += 2) {
        float2 v0[2], v1[2];
        float fr[2];
        #pragma unroll
        for (int j = 0; j < 2; j++) {
            const float cb = s_cb[a + j], sb = s_sb[a + j];
            const float px = fmaf(cb, X, sb * Y);
            const float py = fmaf(-sb, X, cb * Y);
            const float f  = __fdividef(576.0f, 576.0f + py);
            const float s  = fmaf(px, f, 287.5f);
            const int i0   = __float2int_rd(s);
            fr[j] = s - (float)i0;
            const float2* __restrict__ row = &g_pad[(a + j) * PADW + POFF];
            v0[j] = row[i0];
            v1[j] = row[i0 + 1];
        }
        #pragma unroll
        for (int j = 0; j < 2; j++) {
            const float w0 = 1.0f - fr[j];
            accA = fmaf(v0[j].x, w0, accA);
            accA = fmaf(v1[j].x, fr[j], accA);
            accB = fmaf(v0[j].y, w0, accB);
            accB = fmaf(v1[j].y, fr[j], accB);
        }
    }
    const int p = y * W_IMG + x;
    g_img[p]    = accA;
    img_sino[p] = accB;
}

// ---------------------------------------------------------------------------
// Kernel 3: conv3 (2->1, 3x3, pad1), smem-tiled (2 global loads per thread).
// ---------------------------------------------------------------------------
#define DTX 32
#define DTY 8
__global__ void __launch_bounds__(DTX * DTY) conv3_kernel(
    const float* __restrict__ w3, const float* __restrict__ b3,
    const float* __restrict__ img_sino,
    float* __restrict__ img_pred)
{
    __shared__ float sI[DTY + 2][DTX + 2];
    __shared__ float sS[DTY + 2][DTX + 2];
    __shared__ float s_w[18];
    __shared__ float s_b;

    const int tid = threadIdx.y * DTX + threadIdx.x;
    if (tid < 18) s_w[tid] = w3[tid];
    if (tid == 18) s_b = b3[0];

    const int bx0 = blockIdx.x * DTX, by0 = blockIdx.y * DTY;
    for (int i = tid; i < (DTY + 2) * (DTX + 2); i += DTX * DTY) {
        int ly = i / (DTX + 2), lx = i % (DTX + 2);
        int gy = by0 - 1 + ly, gx = bx0 - 1 + lx;
        float vi = 0.0f, vs = 0.0f;
        if ((unsigned)gy < W_IMG && (unsigned)gx < W_IMG) {
            int q = gy * W_IMG + gx;
            vi = g_img[q];
            vs = __ldg(&img_sino[q]);
        }
        sI[ly][lx] = vi;
        sS[ly][lx] = vs;
    }
    __syncthreads();

    const int tx = threadIdx.x, ty = threadIdx.y;
    float acc = s_b;
    #pragma unroll
    for (int ky = 0; ky < 3; ky++)
        #pragma unroll
        for (int kx = 0; kx < 3; kx++) {
            acc = fmaf(sI[ty + ky][tx + kx], s_w[ky * 3 + kx],     acc);
            acc = fmaf(sS[ty + ky][tx + kx], s_w[9 + ky * 3 + kx], acc);
        }
    img_pred[(by0 + ty) * W_IMG + bx0 + tx] = acc;
}

// ---------------------------------------------------------------------------
extern "C" void kernel_launch(void* const* d_in, const int* in_sizes, int n_in,
                              void* d_out, int out_size)
{
    const float* sino   = (const float*)d_in[0];
    const float* angles = (const float*)d_in[1];
    const float* w1     = (const float*)d_in[2];
    const float* b1     = (const float*)d_in[3];
    const float* w2     = (const float*)d_in[4];
    const float* b2     = (const float*)d_in[5];
    const float* w3     = (const float*)d_in[6];
    const float* b3     = (const float*)d_in[7];

    float* out       = (float*)d_out;
    float* sino_pred = out;                               // 192*576 = 110592
    float* img_sino  = out + A_ANG * DDET;                // 384*384 = 147456
    float* img_pred  = out + A_ANG * DDET + W_IMG * W_IMG;

    precompute_kernel<<<1, 640>>>(w1, b1, w2, b2);

    dim3 grid1(DDET / CTX, A_ANG / CTY);
    dim3 block1(CTX, CTY);
    conv12_kernel<<<grid1, block1>>>(sino, b2, sino_pred);

    dim3 grid2(W_IMG / 16, W_IMG / 16);
    backproj_kernel<<<grid2, 256>>>(angles, img_sino);

    dim3 grid3(W_IMG / DTX, W_IMG / DTY);
    dim3 block3(DTX, DTY);
    conv3_kernel<<<grid3, block3>>>(w3, b3, img_sino, img_pred);
}

// round 8
// speedup vs baseline: 1.6265x; 1.0386x over previous
#include <cuda_runtime.h>

#define A_ANG 192
#define DDET  576
#define W_IMG 384
#define PADW  704
#define POFF  64

// Scratch (__device__ globals: allocation-free). g_pad4 is zero-initialized at
// module load; padding slots are never written, so they stay zero across all
// graph replays (out-of-range detector taps contribute exactly 0).
// g_pad4[a][i] = (sino[a][i], pred[a][i], sino[a][i+1], pred[a][i+1])
// Valid gather base indices i0 span [-20, 594] (exact bound over the pixel disc).
__device__ float4 g_pad4[A_ANG * PADW];    // 2.0 MB packed gather table
__device__ float  g_img[W_IMG * W_IMG];    // backprojection of raw sino
__device__ float  g_G[625];                // G[d][e] = sum_c w2[c,d]*w1[c,e]
__device__ float  g_B[25];                 // B[d]    = sum_c w2[c,d]*b1[c]
__device__ float  g_W[81];                 // interior 9x9 composite kernel
__device__ float  g_bias[1];               // b2 + sum_d B[d]

// ---------------------------------------------------------------------------
// Kernel 0: build composite-conv tables (1 block, trivial cost)
// ---------------------------------------------------------------------------
__global__ void __launch_bounds__(640) precompute_kernel(
    const float* __restrict__ w1, const float* __restrict__ b1,
    const float* __restrict__ w2, const float* __restrict__ b2)
{
    __shared__ float sG[625];
    const int tid = threadIdx.x;
    if (tid < 625) {
        int d = tid / 25, e = tid % 25;
        float g = 0.0f;
        #pragma unroll
        for (int c = 0; c < 16; c++) g = fmaf(w2[c * 25 + d], w1[c * 25 + e], g);
        sG[tid] = g;
        g_G[tid] = g;
    }
    if (tid < 25) {
        float s = 0.0f;
        #pragma unroll
        for (int c = 0; c < 16; c++) s = fmaf(w2[c * 25 + tid], b1[c], s);
        g_B[tid] = s;
    }
    __syncthreads();
    if (tid < 81) {
        int tty = tid / 9, ttx = tid % 9;
        float w = 0.0f;
        for (int dy = 0; dy < 5; dy++) {
            int ey = tty - dy; if (ey < 0 || ey > 4) continue;
            for (int dx = 0; dx < 5; dx++) {
                int ex = ttx - dx; if (ex < 0 || ex > 4) continue;
                w += sG[(dy * 5 + dx) * 25 + ey * 5 + ex];
            }
        }
        g_W[tid] = w;
    }
    if (tid == 0) {
        float bias = b2[0];
        #pragma unroll
        for (int c = 0; c < 16; c++) {
            float s2 = 0.0f;
            #pragma unroll
            for (int d = 0; d < 25; d++) s2 += w2[c * 25 + d];
            bias = fmaf(s2, b1[c], bias);
        }
        g_bias[0] = bias;
    }
}

// ---------------------------------------------------------------------------
// Kernel 1: composite conv (sino -> sino_pred), writes packed float4 table.
// Interior pixels: 9x9 kernel W (81 FMA). Border pixels: exact per-d formula.
// Each thread writes its (sino, pred) pair into slot gx (.xy) and slot gx-1
// (.zw), building the (i, i+1) packed gather table.
// ---------------------------------------------------------------------------
#define CTX 32
#define CTY 8
__global__ void __launch_bounds__(CTX * CTY) conv12_kernel(
    const float* __restrict__ sino,
    const float* __restrict__ b2,
    float* __restrict__ sino_pred)
{
    __shared__ float t[CTY + 8][CTX + 8];   // 16 x 40, halo 4, zero-padded
    __shared__ float sW[81];
    __shared__ float sG[625];
    __shared__ float sB[25];
    __shared__ float sbias;

    const int tid = threadIdx.y * CTX + threadIdx.x;
    if (tid < 81) sW[tid] = g_W[tid];
    for (int i = tid; i < 625; i += CTX * CTY) sG[i] = g_G[i];
    if (tid < 25) sB[tid] = g_B[tid];
    if (tid == 255) sbias = g_bias[0];

    const int bx0 = blockIdx.x * CTX, by0 = blockIdx.y * CTY;
    for (int i = tid; i < (CTY + 8) * (CTX + 8); i += CTX * CTY) {
        int ly = i / (CTX + 8), lx = i % (CTX + 8);
        int gy = by0 - 4 + ly, gx = bx0 - 4 + lx;
        float v = 0.0f;
        if ((unsigned)gy < A_ANG && (unsigned)gx < DDET) v = sino[gy * DDET + gx];
        t[ly][lx] = v;
    }
    __syncthreads();

    const int tx = threadIdx.x, ty = threadIdx.y;
    const int gx = bx0 + tx, gy = by0 + ty;
    float acc;
    const bool interior = (gy >= 2) && (gy <= A_ANG - 3) && (gx >= 2) && (gx <= DDET - 3);
    if (interior) {
        acc = sbias;
        #pragma unroll
        for (int a = 0; a < 9; a++)
            #pragma unroll
            for (int b = 0; b < 9; b++)
                acc = fmaf(t[ty + a][tx + b], sW[a * 9 + b], acc);
    } else {
        acc = b2[0];
        for (int dy = 0; dy < 5; dy++) {
            int hy = gy + dy - 2; if ((unsigned)hy >= A_ANG) continue;
            for (int dx = 0; dx < 5; dx++) {
                int hx = gx + dx - 2; if ((unsigned)hx >= DDET) continue;
                float a2 = sB[dy * 5 + dx];
                #pragma unroll
                for (int ey = 0; ey < 5; ey++)
                    #pragma unroll
                    for (int ex = 0; ex < 5; ex++)
                        a2 = fmaf(t[ty + dy + ey][tx + dx + ex],
                                  sG[(dy * 5 + dx) * 25 + ey * 5 + ex], a2);
                acc += a2;
            }
        }
    }
    sino_pred[gy * DDET + gx] = acc;

    const float sv = t[ty + 4][tx + 4];
    const int base = gy * PADW + POFF + gx;
    float2* slot_lo = (float2*)&g_pad4[base];          // .xy of slot gx
    float2* slot_hi = (float2*)&g_pad4[base - 1] + 1;  // .zw of slot gx-1
    *slot_lo = make_float2(sv, acc);
    *slot_hi = make_float2(sv, acc);
}

// ---------------------------------------------------------------------------
// Kernel 2: dual fan-beam backprojection, 16x16 pixel tiles (L1 locality),
// single LDG.128 per pixel-angle, 4-angle unroll = 4 independent chains.
// ---------------------------------------------------------------------------
__global__ void __launch_bounds__(256) backproj_kernel(
    const float* __restrict__ angles,
    float* __restrict__ img_sino)
{
    __shared__ float2 s_ang[A_ANG];
    const int tid = threadIdx.x;
    if (tid < A_ANG) {
        float sv, cv;
        sincosf(angles[tid], &sv, &cv);
        s_ang[tid] = make_float2(cv, sv);
    }
    __syncthreads();

    const int tx = tid & 15, ty = tid >> 4;
    const int x = blockIdx.x * 16 + tx;
    const int y = blockIdx.y * 16 + ty;
    const float X = (float)x - 191.5f;
    const float Y = (float)y - 191.5f;

    float accA = 0.f, accB = 0.f;
    for (int a = 0; a < A_ANG; a += 4) {
        float4 v[4];
        float fr[4];
        #pragma unroll
        for (int j = 0; j < 4; j++) {
            const float2 cs = s_ang[a + j];
            const float px = fmaf(cs.x, X, cs.y * Y);
            const float py = fmaf(-cs.y, X, cs.x * Y);
            const float f  = __fdividef(576.0f, 576.0f + py);
            const float s  = fmaf(px, f, 287.5f);
            const int i0   = __float2int_rd(s);
            fr[j] = s - (float)i0;
            v[j] = __ldg(&g_pad4[(a + j) * PADW + POFF + i0]);
        }
        #pragma unroll
        for (int j = 0; j < 4; j++) {
            const float w0 = 1.0f - fr[j];
            accA = fmaf(v[j].x, w0, accA);
            accA = fmaf(v[j].z, fr[j], accA);
            accB = fmaf(v[j].y, w0, accB);
            accB = fmaf(v[j].w, fr[j], accB);
        }
    }
    const int p = y * W_IMG + x;
    g_img[p]    = accA;
    img_sino[p] = accB;
}

// ---------------------------------------------------------------------------
// Kernel 3: conv3 (2->1, 3x3, pad1), smem-tiled, 32x16 blocks.
// ---------------------------------------------------------------------------
#define DTX 32
#define DTY 16
__global__ void __launch_bounds__(DTX * DTY) conv3_kernel(
    const float* __restrict__ w3, const float* __restrict__ b3,
    const float* __restrict__ img_sino,
    float* __restrict__ img_pred)
{
    __shared__ float sI[DTY + 2][DTX + 2];
    __shared__ float sS[DTY + 2][DTX + 2];
    __shared__ float s_w[18];
    __shared__ float s_b;

    const int tid = threadIdx.y * DTX + threadIdx.x;
    if (tid < 18) s_w[tid] = w3[tid];
    if (tid == 18) s_b = b3[0];

    const int bx0 = blockIdx.x * DTX, by0 = blockIdx.y * DTY;
    for (int i = tid; i < (DTY + 2) * (DTX + 2); i += DTX * DTY) {
        int ly = i / (DTX + 2), lx = i % (DTX + 2);
        int gy = by0 - 1 + ly, gx = bx0 - 1 + lx;
        float vi = 0.0f, vs = 0.0f;
        if ((unsigned)gy < W_IMG && (unsigned)gx < W_IMG) {
            int q = gy * W_IMG + gx;
            vi = g_img[q];
            vs = __ldg(&img_sino[q]);
        }
        sI[ly][lx] = vi;
        sS[ly][lx] = vs;
    }
    __syncthreads();

    const int tx = threadIdx.x, ty = threadIdx.y;
    float acc = s_b;
    #pragma unroll
    for (int ky = 0; ky < 3; ky++)
        #pragma unroll
        for (int kx = 0; kx < 3; kx++) {
            acc = fmaf(sI[ty + ky][tx + kx], s_w[ky * 3 + kx],     acc);
            acc = fmaf(sS[ty + ky][tx + kx], s_w[9 + ky * 3 + kx], acc);
        }
    img_pred[(by0 + ty) * W_IMG + bx0 + tx] = acc;
}

// ---------------------------------------------------------------------------
extern "C" void kernel_launch(void* const* d_in, const int* in_sizes, int n_in,
                              void* d_out, int out_size)
{
    const float* sino   = (const float*)d_in[0];
    const float* angles = (const float*)d_in[1];
    const float* w1     = (const float*)d_in[2];
    const float* b1     = (const float*)d_in[3];
    const float* w2     = (const float*)d_in[4];
    const float* b2     = (const float*)d_in[5];
    const float* w3     = (const float*)d_in[6];
    const float* b3     = (const float*)d_in[7];

    float* out       = (float*)d_out;
    float* sino_pred = out;                               // 192*576 = 110592
    float* img_sino  = out + A_ANG * DDET;                // 384*384 = 147456
    float* img_pred  = out + A_ANG * DDET + W_IMG * W_IMG;

    precompute_kernel<<<1, 640>>>(w1, b1, w2, b2);

    dim3 grid1(DDET / CTX, A_ANG / CTY);
    dim3 block1(CTX, CTY);
    conv12_kernel<<<grid1, block1>>>(sino, b2, sino_pred);

    dim3 grid2(W_IMG / 16, W_IMG / 16);
    backproj_kernel<<<grid2, 256>>>(angles, img_sino);

    dim3 grid3(W_IMG / DTX, W_IMG / DTY);
    dim3 block3(DTX, DTY);
    conv3_kernel<<<grid3, block3>>>(w3, b3, img_sino, img_pred);
}

// round 9
// speedup vs baseline: 1.6620x; 1.0218x over previous
#include <cuda_runtime.h>

#define A_ANG 192
#define DDET  576
#define W_IMG 384
#define PADW  672
#define POFF  24

// Scratch (__device__ globals: allocation-free). g_pad is zero-initialized at
// module load; padding slots are never written, so they stay zero across all
// graph replays (out-of-range detector taps contribute exactly 0).
// Valid gather base indices i0 span [-20, 594] (exact bound over pixel disc).
__device__ float2 g_pad[A_ANG * PADW];     // 1.0 MB packed (sino, pred) table
__device__ float  g_img[W_IMG * W_IMG];    // backprojection of raw sino
__device__ float  g_G[625];                // G[d][e] = sum_c w2[c,d]*w1[c,e]
__device__ float  g_B[25];                 // B[d]    = sum_c w2[c,d]*b1[c]
__device__ float  g_W[81];                 // interior 9x9 composite kernel
__device__ float  g_bias[1];               // b2 + sum_d B[d]

// ---------------------------------------------------------------------------
// Kernel 0: build composite-conv tables (1 block, trivial cost)
// ---------------------------------------------------------------------------
__global__ void __launch_bounds__(640) precompute_kernel(
    const float* __restrict__ w1, const float* __restrict__ b1,
    const float* __restrict__ w2, const float* __restrict__ b2)
{
    __shared__ float sG[625];
    const int tid = threadIdx.x;
    if (tid < 625) {
        int d = tid / 25, e = tid % 25;
        float g = 0.0f;
        #pragma unroll
        for (int c = 0; c < 16; c++) g = fmaf(w2[c * 25 + d], w1[c * 25 + e], g);
        sG[tid] = g;
        g_G[tid] = g;
    }
    if (tid < 25) {
        float s = 0.0f;
        #pragma unroll
        for (int c = 0; c < 16; c++) s = fmaf(w2[c * 25 + tid], b1[c], s);
        g_B[tid] = s;
    }
    __syncthreads();
    if (tid < 81) {
        int tty = tid / 9, ttx = tid % 9;
        float w = 0.0f;
        for (int dy = 0; dy < 5; dy++) {
            int ey = tty - dy; if (ey < 0 || ey > 4) continue;
            for (int dx = 0; dx < 5; dx++) {
                int ex = ttx - dx; if (ex < 0 || ex > 4) continue;
                w += sG[(dy * 5 + dx) * 25 + ey * 5 + ex];
            }
        }
        g_W[tid] = w;
    }
    if (tid == 0) {
        float bias = b2[0];
        #pragma unroll
        for (int c = 0; c < 16; c++) {
            float s2 = 0.0f;
            #pragma unroll
            for (int d = 0; d < 25; d++) s2 += w2[c * 25 + d];
            bias = fmaf(s2, b1[c], bias);
        }
        g_bias[0] = bias;
    }
}

// ---------------------------------------------------------------------------
// Kernel 1: composite conv (sino -> sino_pred), writes packed padded sinogram.
// Interior pixels: 9x9 kernel W (81 FMA). Border pixels: exact per-d formula.
// ---------------------------------------------------------------------------
#define CTX 32
#define CTY 8
__global__ void __launch_bounds__(CTX * CTY) conv12_kernel(
    const float* __restrict__ sino,
    const float* __restrict__ b2,
    float* __restrict__ sino_pred)
{
    __shared__ float t[CTY + 8][CTX + 8];   // 16 x 40, halo 4, zero-padded
    __shared__ float sW[81];
    __shared__ float sG[625];
    __shared__ float sB[25];
    __shared__ float sbias;

    const int tid = threadIdx.y * CTX + threadIdx.x;
    if (tid < 81) sW[tid] = g_W[tid];
    for (int i = tid; i < 625; i += CTX * CTY) sG[i] = g_G[i];
    if (tid < 25) sB[tid] = g_B[tid];
    if (tid == 255) sbias = g_bias[0];

    const int bx0 = blockIdx.x * CTX, by0 = blockIdx.y * CTY;
    for (int i = tid; i < (CTY + 8) * (CTX + 8); i += CTX * CTY) {
        int ly = i / (CTX + 8), lx = i % (CTX + 8);
        int gy = by0 - 4 + ly, gx = bx0 - 4 + lx;
        float v = 0.0f;
        if ((unsigned)gy < A_ANG && (unsigned)gx < DDET) v = sino[gy * DDET + gx];
        t[ly][lx] = v;
    }
    __syncthreads();

    const int tx = threadIdx.x, ty = threadIdx.y;
    const int gx = bx0 + tx, gy = by0 + ty;
    float acc;
    const bool interior = (gy >= 2) && (gy <= A_ANG - 3) && (gx >= 2) && (gx <= DDET - 3);
    if (interior) {
        acc = sbias;
        #pragma unroll
        for (int a = 0; a < 9; a++)
            #pragma unroll
            for (int b = 0; b < 9; b++)
                acc = fmaf(t[ty + a][tx + b], sW[a * 9 + b], acc);
    } else {
        acc = b2[0];
        for (int dy = 0; dy < 5; dy++) {
            int hy = gy + dy - 2; if ((unsigned)hy >= A_ANG) continue;
            for (int dx = 0; dx < 5; dx++) {
                int hx = gx + dx - 2; if ((unsigned)hx >= DDET) continue;
                float a2 = sB[dy * 5 + dx];
                #pragma unroll
                for (int ey = 0; ey < 5; ey++)
                    #pragma unroll
                    for (int ex = 0; ex < 5; ex++)
                        a2 = fmaf(t[ty + dy + ey][tx + dx + ex],
                                  sG[(dy * 5 + dx) * 25 + ey * 5 + ex], a2);
                acc += a2;
            }
        }
    }
    const int idx = gy * DDET + gx;
    sino_pred[idx] = acc;
    g_pad[gy * PADW + POFF + gx] = make_float2(t[ty + 4][tx + 4], acc);
}

// ---------------------------------------------------------------------------
// Kernel 2: dual fan-beam backprojection.
// 32x32 pixel tile per 1024-thread block (144 blocks ~= 1/SM, single wave).
// Per-block L1 working set ~100KB across all angles -> L1-resident with
// exactly one block per SM (reg cap from launch_bounds enforces this).
// Warp footprint 8x4 pixels; 2-angle unroll = 4 independent gather chains.
// ---------------------------------------------------------------------------
__global__ void __launch_bounds__(1024) backproj_kernel(
    const float* __restrict__ angles,
    float* __restrict__ img_sino)
{
    __shared__ float2 s_ang[A_ANG];
    const int tid = threadIdx.x;
    if (tid < A_ANG) {
        float sv, cv;
        sincosf(angles[tid], &sv, &cv);
        s_ang[tid] = make_float2(cv, sv);
    }
    __syncthreads();

    // warp footprint 8x4; warps tiled 4 across x, 8 down y
    const int lane = tid & 31, wid = tid >> 5;
    const int lx = lane & 7,  ly = lane >> 3;      // 8 x 4
    const int wx = wid & 3,   wy = wid >> 2;       // 4 x 8
    const int x = blockIdx.x * 32 + wx * 8 + lx;
    const int y = blockIdx.y * 32 + wy * 4 + ly;
    const float X = (float)x - 191.5f;
    const float Y = (float)y - 191.5f;

    float accA = 0.f, accB = 0.f;
    for (int a = 0; a < A_ANG; a += 2) {
        float2 v0[2], v1[2];
        float fr[2];
        #pragma unroll
        for (int j = 0; j < 2; j++) {
            const float2 cs = s_ang[a + j];
            const float px = fmaf(cs.x, X, cs.y * Y);
            const float py = fmaf(-cs.y, X, cs.x * Y);
            const float f  = __fdividef(576.0f, 576.0f + py);
            const float s  = fmaf(px, f, 287.5f);
            const int i0   = __float2int_rd(s);
            fr[j] = s - (float)i0;
            const float2* __restrict__ row = &g_pad[(a + j) * PADW + POFF];
            v0[j] = __ldg(&row[i0]);
            v1[j] = __ldg(&row[i0 + 1]);
        }
        #pragma unroll
        for (int j = 0; j < 2; j++) {
            const float w0 = 1.0f - fr[j];
            accA = fmaf(v0[j].x, w0, accA);
            accA = fmaf(v1[j].x, fr[j], accA);
            accB = fmaf(v0[j].y, w0, accB);
            accB = fmaf(v1[j].y, fr[j], accB);
        }
    }
    const int p = y * W_IMG + x;
    g_img[p]    = accA;
    img_sino[p] = accB;
}

// ---------------------------------------------------------------------------
// Kernel 3: conv3 (2->1, 3x3, pad1), smem-tiled, 32x16 blocks.
// ---------------------------------------------------------------------------
#define DTX 32
#define DTY 16
__global__ void __launch_bounds__(DTX * DTY) conv3_kernel(
    const float* __restrict__ w3, const float* __restrict__ b3,
    const float* __restrict__ img_sino,
    float* __restrict__ img_pred)
{
    __shared__ float sI[DTY + 2][DTX + 2];
    __shared__ float sS[DTY + 2][DTX + 2];
    __shared__ float s_w[18];
    __shared__ float s_b;

    const int tid = threadIdx.y * DTX + threadIdx.x;
    if (tid < 18) s_w[tid] = w3[tid];
    if (tid == 18) s_b = b3[0];

    const int bx0 = blockIdx.x * DTX, by0 = blockIdx.y * DTY;
    for (int i = tid; i < (DTY + 2) * (DTX + 2); i += DTX * DTY) {
        int ly = i / (DTX + 2), lx = i % (DTX + 2);
        int gy = by0 - 1 + ly, gx = bx0 - 1 + lx;
        float vi = 0.0f, vs = 0.0f;
        if ((unsigned)gy < W_IMG && (unsigned)gx < W_IMG) {
            int q = gy * W_IMG + gx;
            vi = g_img[q];
            vs = __ldg(&img_sino[q]);
        }
        sI[ly][lx] = vi;
        sS[ly][lx] = vs;
    }
    __syncthreads();

    const int tx = threadIdx.x, ty = threadIdx.y;
    float acc = s_b;
    #pragma unroll
    for (int ky = 0; ky < 3; ky++)
        #pragma unroll
        for (int kx = 0; kx < 3; kx++) {
            acc = fmaf(sI[ty + ky][tx + kx], s_w[ky * 3 + kx],     acc);
            acc = fmaf(sS[ty + ky][tx + kx], s_w[9 + ky * 3 + kx], acc);
        }
    img_pred[(by0 + ty) * W_IMG + bx0 + tx] = acc;
}

// ---------------------------------------------------------------------------
extern "C" void kernel_launch(void* const* d_in, const int* in_sizes, int n_in,
                              void* d_out, int out_size)
{
    const float* sino   = (const float*)d_in[0];
    const float* angles = (const float*)d_in[1];
    const float* w1     = (const float*)d_in[2];
    const float* b1     = (const float*)d_in[3];
    const float* w2     = (const float*)d_in[4];
    const float* b2     = (const float*)d_in[5];
    const float* w3     = (const float*)d_in[6];
    const float* b3     = (const float*)d_in[7];

    float* out       = (float*)d_out;
    float* sino_pred = out;                               // 192*576 = 110592
    float* img_sino  = out + A_ANG * DDET;                // 384*384 = 147456
    float* img_pred  = out + A_ANG * DDET + W_IMG * W_IMG;

    precompute_kernel<<<1, 640>>>(w1, b1, w2, b2);

    dim3 grid1(DDET / CTX, A_ANG / CTY);
    dim3 block1(CTX, CTY);
    conv12_kernel<<<grid1, block1>>>(sino, b2, sino_pred);

    dim3 grid2(W_IMG / 32, W_IMG / 32);
    backproj_kernel<<<grid2, 1024>>>(angles, img_sino);

    dim3 grid3(W_IMG / DTX, W_IMG / DTY);
    dim3 block3(DTX, DTY);
    conv3_kernel<<<grid3, block3>>>(w3, b3, img_sino, img_pred);
}